// round 8
// baseline (speedup 1.0000x reference)
#include <cuda_runtime.h>

#define NQ 8
#define HD 256
#define S_TOT 8192
#define PAST 8191
#define HID 1536
#define INTER 6144
#define QDIM 2048
#define SCALE 0.0625f
#define NCHUNK 512          // 8192 / 16
#define CHUNK 16

// -------- scratch (device globals) --------
__device__ float g_qkvp[2 * 2560];         // per-half QKV partials (no bias): [half][col]
__device__ float g_avpart[NCHUNK * 2048];  // per-chunk partial AV: [c][h*256+d]
__device__ float g_stm[NCHUNK * 8];        // per-(chunk,head) local max
__device__ float g_stl[NCHUNK * 8];        // per-(chunk,head) local sum
__device__ float g_attn[QDIM];             // final attention output
__device__ float g_h1[HID];                // post-attention residual (preset x+bo, atomics add Wo part)
__device__ float g_mid[INTER];             // gelu(gate)*up

static __device__ __forceinline__ float4 f4add(float4 a, float4 b) {
    a.x += b.x; a.y += b.y; a.z += b.z; a.w += b.w; return a;
}
static __device__ __forceinline__ void f4fma(float4& a, float s, float4 w) {
    a.x += s * w.x; a.y += s * w.y; a.z += s * w.z; a.w += s * w.w;
}
static __device__ __forceinline__ float gelu_exact(float v) {
    return 0.5f * v * (1.0f + erff(v * 0.70710678118654752f));
}
template<int PMIN>
static __device__ __forceinline__ float4 wred(float4 v) {
#pragma unroll
    for (int off = 16; off >= PMIN; off >>= 1) {
        v.x += __shfl_xor_sync(0xffffffffu, v.x, off);
        v.y += __shfl_xor_sync(0xffffffffu, v.y, off);
        v.z += __shfl_xor_sync(0xffffffffu, v.z, off);
        v.w += __shfl_xor_sync(0xffffffffu, v.w, off);
    }
    return v;
}
// assemble one float4 of q/k/v from the two R-split partials + bias
static __device__ __forceinline__ float4 qkv_f4(const float* __restrict__ bias,
                                                int base, int boff) {
    float4 p0 = *(const float4*)&g_qkvp[base + boff];
    float4 p1 = *(const float4*)&g_qkvp[2560 + base + boff];
    float4 b  = *(const float4*)&bias[boff - (base == 2048 ? 2048 : (base == 2304 ? 2304 : 0)) + base - base];
    // note: callers pass boff relative to base below instead; keep simple:
    return p0; // unused (see specialized versions below)
}

// ============ K1: QKV projection partials (R-split by 2) ============
// 640 blocks x 512 thr. Block = (colTile of 8, half of fan_in). rows_pt=3.
__global__ __launch_bounds__(512) void k_qkv(
        const float* __restrict__ x,
        const float* __restrict__ Wq, const float* __restrict__ Wk,
        const float* __restrict__ Wv) {
    __shared__ float4 part[16 * 2];
    int t = threadIdx.x, lane = t & 31, wid = t >> 5;
    int c4 = t & 1, rg = t >> 1;
    int b = blockIdx.x;
    const float* W; int ld, wcol, colBase, half;
    if (b < 512)      { int bb = b;       half = bb & 1; int ct = bb >> 1; W = Wq; ld = 2048; wcol = ct * 8;  colBase = ct * 8; }
    else if (b < 576) { int bb = b - 512; half = bb & 1; int ct = bb >> 1; W = Wk; ld = 256;  wcol = ct * 8;  colBase = 2048 + ct * 8; }
    else              { int bb = b - 576; half = bb & 1; int ct = bb >> 1; W = Wv; ld = 256;  wcol = ct * 8;  colBase = 2304 + ct * 8; }
    const float* wp = W + wcol + c4 * 4;
    int r0 = half * 768 + rg * 3;
    float4 w0 = *(const float4*)(wp + (size_t)(r0    ) * ld);
    float4 w1 = *(const float4*)(wp + (size_t)(r0 + 1) * ld);
    float4 w2 = *(const float4*)(wp + (size_t)(r0 + 2) * ld);
    float x0 = __ldg(x + r0), x1 = __ldg(x + r0 + 1), x2 = __ldg(x + r0 + 2);
    float4 acc = make_float4(0.f, 0.f, 0.f, 0.f);
    f4fma(acc, x0, w0); f4fma(acc, x1, w1); f4fma(acc, x2, w2);
    acc = wred<2>(acc);
    if (lane < 2) part[wid * 2 + lane] = acc;
    __syncthreads();
    if (t < 2) {
        float4 s = part[t];
#pragma unroll
        for (int wi = 1; wi < 16; wi++) s = f4add(s, part[wi * 2 + t]);
        *(float4*)&g_qkvp[half * 2560 + colBase + t * 4] = s;
    }
}

// ============ K2: fused flash-decode partial, CHUNK=16 ============
// 512 blocks x 256 thr.
__global__ __launch_bounds__(256) void k_attn(
        const float* __restrict__ kp, const float* __restrict__ vp,
        const float* __restrict__ bq, const float* __restrict__ bk,
        const float* __restrict__ bv) {
    __shared__ float s_sm[8][CHUNK];
    __shared__ float4 red[4 * 8 * 64];        // 32KB
    int t = threadIdx.x, lane = t & 31, wid = t >> 5;
    int c = blockIdx.x;
    int sBase = c * CHUNK;

    // assemble q for all 8 heads: (p0+p1+bq)*SCALE
    float4 qa[8], qb[8];
#pragma unroll
    for (int h = 0; h < 8; h++) {
        int o = h * 256 + lane * 8;
        float4 p0 = *(const float4*)&g_qkvp[o];
        float4 p1 = *(const float4*)&g_qkvp[2560 + o];
        float4 bb = *(const float4*)&bq[o];
        qa[h] = make_float4((p0.x + p1.x + bb.x) * SCALE, (p0.y + p1.y + bb.y) * SCALE,
                            (p0.z + p1.z + bb.z) * SCALE, (p0.w + p1.w + bb.w) * SCALE);
        p0 = *(const float4*)&g_qkvp[o + 4];
        p1 = *(const float4*)&g_qkvp[2560 + o + 4];
        bb = *(const float4*)&bq[o + 4];
        qb[h] = make_float4((p0.x + p1.x + bb.x) * SCALE, (p0.y + p1.y + bb.y) * SCALE,
                            (p0.z + p1.z + bb.z) * SCALE, (p0.w + p1.w + bb.w) * SCALE);
    }
    // ---- Phase 1: scores; warp wid handles rows wid*2, wid*2+1
    {
        int r0 = sBase + wid * 2, r1 = r0 + 1;
        float4 ka0, kb0, ka1, kb1;
        if (r0 < PAST) {
            ka0 = *(const float4*)(kp + (size_t)r0 * 256 + lane * 8);
            kb0 = *(const float4*)(kp + (size_t)r0 * 256 + lane * 8 + 4);
        } else {
            int o = 2048 + lane * 8;
            float4 p0 = *(const float4*)&g_qkvp[o], p1 = *(const float4*)&g_qkvp[2560 + o];
            float4 bb = *(const float4*)&bk[lane * 8];
            ka0 = make_float4(p0.x + p1.x + bb.x, p0.y + p1.y + bb.y, p0.z + p1.z + bb.z, p0.w + p1.w + bb.w);
            p0 = *(const float4*)&g_qkvp[o + 4]; p1 = *(const float4*)&g_qkvp[2560 + o + 4];
            bb = *(const float4*)&bk[lane * 8 + 4];
            kb0 = make_float4(p0.x + p1.x + bb.x, p0.y + p1.y + bb.y, p0.z + p1.z + bb.z, p0.w + p1.w + bb.w);
        }
        if (r1 < PAST) {
            ka1 = *(const float4*)(kp + (size_t)r1 * 256 + lane * 8);
            kb1 = *(const float4*)(kp + (size_t)r1 * 256 + lane * 8 + 4);
        } else {
            int o = 2048 + lane * 8;
            float4 p0 = *(const float4*)&g_qkvp[o], p1 = *(const float4*)&g_qkvp[2560 + o];
            float4 bb = *(const float4*)&bk[lane * 8];
            ka1 = make_float4(p0.x + p1.x + bb.x, p0.y + p1.y + bb.y, p0.z + p1.z + bb.z, p0.w + p1.w + bb.w);
            p0 = *(const float4*)&g_qkvp[o + 4]; p1 = *(const float4*)&g_qkvp[2560 + o + 4];
            bb = *(const float4*)&bk[lane * 8 + 4];
            kb1 = make_float4(p0.x + p1.x + bb.x, p0.y + p1.y + bb.y, p0.z + p1.z + bb.z, p0.w + p1.w + bb.w);
        }
        float a0[8], a1[8];
#pragma unroll
        for (int h = 0; h < 8; h++) {
            a0[h] = qa[h].x * ka0.x + qa[h].y * ka0.y + qa[h].z * ka0.z + qa[h].w * ka0.w
                  + qb[h].x * kb0.x + qb[h].y * kb0.y + qb[h].z * kb0.z + qb[h].w * kb0.w;
            a1[h] = qa[h].x * ka1.x + qa[h].y * ka1.y + qa[h].z * ka1.z + qa[h].w * ka1.w
                  + qb[h].x * kb1.x + qb[h].y * kb1.y + qb[h].z * kb1.z + qb[h].w * kb1.w;
        }
#pragma unroll
        for (int h = 0; h < 8; h++) {
#pragma unroll
            for (int off = 16; off; off >>= 1) {
                a0[h] += __shfl_xor_sync(0xffffffffu, a0[h], off);
                a1[h] += __shfl_xor_sync(0xffffffffu, a1[h], off);
            }
        }
        if (lane < 8) {
            s_sm[lane][wid * 2]     = a0[lane];
            s_sm[lane][wid * 2 + 1] = a1[lane];
        }
    }
    __syncthreads();
    // ---- Phase 2: per-head local softmax; warp wid = head wid.
    // Lanes read duplicated (lane&15) values: max unaffected, sum halved.
    {
        float s = s_sm[wid][lane & 15];
        float m = s;
#pragma unroll
        for (int off = 16; off; off >>= 1) m = fmaxf(m, __shfl_xor_sync(0xffffffffu, m, off));
        float p = __expf(s - m);
        float l = p;
#pragma unroll
        for (int off = 16; off; off >>= 1) l += __shfl_xor_sync(0xffffffffu, l, off);
        l *= 0.5f;
        if (lane < 16) s_sm[wid][lane] = p;
        if (lane == 0) { g_stm[c * 8 + wid] = m; g_stl[c * 8 + wid] = l; }
    }
    __syncthreads();
    // ---- Phase 3: p.V — group g (4 positions each), d4
    int d4 = t & 63, g = t >> 6;
    float4 v[4];
#pragma unroll
    for (int j = 0; j < 4; j++) {
        int s = sBase + g * 4 + j;
        if (s < PAST) {
            v[j] = *(const float4*)(vp + (size_t)s * 256 + d4 * 4);
        } else {
            int o = 2304 + d4 * 4;
            float4 p0 = *(const float4*)&g_qkvp[o], p1 = *(const float4*)&g_qkvp[2560 + o];
            float4 bb = *(const float4*)&bv[d4 * 4];
            v[j] = make_float4(p0.x + p1.x + bb.x, p0.y + p1.y + bb.y, p0.z + p1.z + bb.z, p0.w + p1.w + bb.w);
        }
    }
    float4 acc[8];
#pragma unroll
    for (int h = 0; h < 8; h++) acc[h] = make_float4(0.f, 0.f, 0.f, 0.f);
#pragma unroll
    for (int j = 0; j < 4; j++) {
        int pos = g * 4 + j;
#pragma unroll
        for (int h = 0; h < 8; h++) f4fma(acc[h], s_sm[h][pos], v[j]);
    }
#pragma unroll
    for (int h = 0; h < 8; h++) red[g * 512 + h * 64 + d4] = acc[h];
    __syncthreads();
    float4* outp = (float4*)(g_avpart + (size_t)c * 2048);
#pragma unroll
    for (int k = 0; k < 2; k++) {
        int o = t + k * 256;
        float4 s = f4add(f4add(red[o], red[512 + o]), f4add(red[1024 + o], red[1536 + o]));
        outp[o] = s;
    }
}

// ============ K3: combine partials -> g_attn; also preset g_h1 = x + bo ============
// 32 blocks x 256 thr. Block handles 16 float4 outputs.
__global__ __launch_bounds__(256) void k_comb(
        const float* __restrict__ x, const float* __restrict__ bo) {
    __shared__ float w_sm[NCHUNK * 8];    // 16KB
    __shared__ float4 red2[256];
    int t = threadIdx.x, lane = t & 31, wid = t >> 5;
    // per-head M, L (warp wid = head); lane covers 16 chunks
    float mv[16], lv[16];
#pragma unroll
    for (int i = 0; i < 16; i++) {
        int c = lane * 16 + i;
        mv[i] = g_stm[c * 8 + wid];
        lv[i] = g_stl[c * 8 + wid];
    }
    float M = mv[0];
#pragma unroll
    for (int i = 1; i < 16; i++) M = fmaxf(M, mv[i]);
#pragma unroll
    for (int off = 16; off; off >>= 1) M = fmaxf(M, __shfl_xor_sync(0xffffffffu, M, off));
    float L = 0.f;
#pragma unroll
    for (int i = 0; i < 16; i++) L += __expf(mv[i] - M) * lv[i];
#pragma unroll
    for (int off = 16; off; off >>= 1) L += __shfl_xor_sync(0xffffffffu, L, off);
    float invL = 1.0f / L;
#pragma unroll
    for (int i = 0; i < 16; i++) {
        int c = lane * 16 + i;
        w_sm[c * 8 + wid] = __expf(mv[i] - M) * invL;
    }
    // preset g_h1 = x + bo (blocks 0..5 cover 1536 floats)
    if (blockIdx.x < 6) {
        int idx = blockIdx.x * 256 + t;
        g_h1[idx] = x[idx] + bo[idx];
    }
    __syncthreads();
    // main: o coalesced across lanes (oLoc = t&15), sl = chunk slice
    int oLoc = t & 15, sl = t >> 4;
    int o = blockIdx.x * 16 + oLoc;
    int h = o >> 6;
    float4 acc = make_float4(0.f, 0.f, 0.f, 0.f);
#pragma unroll
    for (int b = 0; b < 4; b++) {
        float4 vv[8];
#pragma unroll
        for (int i = 0; i < 8; i++) {
            int cidx = sl + (b * 8 + i) * 16;
            vv[i] = *(const float4*)(g_avpart + (size_t)cidx * 2048 + o * 4);
        }
#pragma unroll
        for (int i = 0; i < 8; i++) {
            int cidx = sl + (b * 8 + i) * 16;
            f4fma(acc, w_sm[cidx * 8 + h], vv[i]);
        }
    }
    red2[t] = acc;
    __syncthreads();
    if (t < 16) {
        float4 s = red2[t];
#pragma unroll
        for (int j = 1; j < 16; j++) s = f4add(s, red2[t + 16 * j]);
        ((float4*)g_attn)[blockIdx.x * 16 + t] = s;
    }
}

// ============ K4: g_h1 += attn @ Wo  (R-split by 2, atomic combine) ============
// 384 blocks x 512 thr. rows_pt=4.
__global__ __launch_bounds__(512) void k_wo(const float* __restrict__ Wo) {
    __shared__ float4 part[16 * 2];
    int t = threadIdx.x, lane = t & 31, wid = t >> 5;
    int c4 = t & 1, rg = t >> 1;
    int colTile = blockIdx.x >> 1, half = blockIdx.x & 1;
    int colBase = colTile * 8;
    const float* wp = Wo + colBase + c4 * 4;
    int r0 = half * 1024 + rg * 4;
    float4 w0 = *(const float4*)(wp + (size_t)(r0    ) * 1536);
    float4 w1 = *(const float4*)(wp + (size_t)(r0 + 1) * 1536);
    float4 w2 = *(const float4*)(wp + (size_t)(r0 + 2) * 1536);
    float4 w3 = *(const float4*)(wp + (size_t)(r0 + 3) * 1536);
    float x0 = g_attn[r0], x1 = g_attn[r0 + 1], x2 = g_attn[r0 + 2], x3 = g_attn[r0 + 3];
    float4 acc = make_float4(0.f, 0.f, 0.f, 0.f);
    f4fma(acc, x0, w0); f4fma(acc, x1, w1); f4fma(acc, x2, w2); f4fma(acc, x3, w3);
    acc = wred<2>(acc);
    if (lane < 2) part[wid * 2 + lane] = acc;
    __syncthreads();
    if (t < 2) {
        float4 s = part[t];
#pragma unroll
        for (int wi = 1; wi < 16; wi++) s = f4add(s, part[wi * 2 + t]);
        atomicAdd(&((float4*)g_h1)[colTile * 2 + t], s);
    }
}

// ============ K5: mid = gelu(h1@Wg+bg)*(h1@Wu+bu); preset out = h1+bd ============
// 768 blocks x 512 thr. Block owns 8 cols of both; rows_pt=6 per matrix.
__global__ __launch_bounds__(512) void k_gateup(
        const float* __restrict__ Wg, const float* __restrict__ bg,
        const float* __restrict__ Wu, const float* __restrict__ bu,
        const float* __restrict__ bd, float* __restrict__ out) {
    __shared__ float4 pg[16 * 2], pu[16 * 2];
    int t = threadIdx.x, lane = t & 31, wid = t >> 5;
    // preset out = g_h1 + bd (blocks 0..2 cover 1536 floats)
    if (blockIdx.x < 3) {
        int idx = blockIdx.x * 512 + t;
        out[idx] = g_h1[idx] + bd[idx];
    }
    int c4 = t & 1, rg = t >> 1;
    int colBase = blockIdx.x * 8;
    const float* wg = Wg + colBase + c4 * 4;
    const float* wu = Wu + colBase + c4 * 4;
    float4 ag = make_float4(0.f, 0.f, 0.f, 0.f);
    float4 au = make_float4(0.f, 0.f, 0.f, 0.f);
    int r0 = rg * 6;
#pragma unroll
    for (int b = 0; b < 2; b++) {
        float4 wa0 = *(const float4*)(wg + (size_t)(r0 + b * 3    ) * 6144);
        float4 wa1 = *(const float4*)(wg + (size_t)(r0 + b * 3 + 1) * 6144);
        float4 wa2 = *(const float4*)(wg + (size_t)(r0 + b * 3 + 2) * 6144);
        float4 wb0 = *(const float4*)(wu + (size_t)(r0 + b * 3    ) * 6144);
        float4 wb1 = *(const float4*)(wu + (size_t)(r0 + b * 3 + 1) * 6144);
        float4 wb2 = *(const float4*)(wu + (size_t)(r0 + b * 3 + 2) * 6144);
        float x0 = g_h1[r0 + b * 3], x1 = g_h1[r0 + b * 3 + 1], x2 = g_h1[r0 + b * 3 + 2];
        f4fma(ag, x0, wa0); f4fma(ag, x1, wa1); f4fma(ag, x2, wa2);
        f4fma(au, x0, wb0); f4fma(au, x1, wb1); f4fma(au, x2, wb2);
    }
    ag = wred<2>(ag);
    au = wred<2>(au);
    if (lane < 2) { pg[wid * 2 + lane] = ag; pu[wid * 2 + lane] = au; }
    __syncthreads();
    if (t < 2) {
        float4 sg = pg[t], su = pu[t];
#pragma unroll
        for (int wi = 1; wi < 16; wi++) { sg = f4add(sg, pg[wi * 2 + t]); su = f4add(su, pu[wi * 2 + t]); }
        int col = colBase + t * 4;
        float4 gv = f4add(sg, *(const float4*)(bg + col));
        float4 uv = f4add(su, *(const float4*)(bu + col));
        float4 o;
        o.x = gelu_exact(gv.x) * uv.x;
        o.y = gelu_exact(gv.y) * uv.y;
        o.z = gelu_exact(gv.z) * uv.z;
        o.w = gelu_exact(gv.w) * uv.w;
        *(float4*)&g_mid[col] = o;
    }
}

// ============ K6: out += mid @ Wd  (R-split by 2, atomic combine) ============
// 384 blocks x 512 thr. rows_pt=12 in 3 batches of 4.
__global__ __launch_bounds__(512) void k_down(
        const float* __restrict__ Wd, float* __restrict__ out) {
    __shared__ float4 part[16 * 2];
    int t = threadIdx.x, lane = t & 31, wid = t >> 5;
    int c4 = t & 1, rg = t >> 1;
    int colTile = blockIdx.x >> 1, half = blockIdx.x & 1;
    int colBase = colTile * 8;
    const float* wp = Wd + colBase + c4 * 4;
    float4 acc = make_float4(0.f, 0.f, 0.f, 0.f);
    int r0 = half * 3072 + rg * 12;
#pragma unroll
    for (int b = 0; b < 3; b++) {
        float4 w0 = *(const float4*)(wp + (size_t)(r0 + b * 4    ) * 1536);
        float4 w1 = *(const float4*)(wp + (size_t)(r0 + b * 4 + 1) * 1536);
        float4 w2 = *(const float4*)(wp + (size_t)(r0 + b * 4 + 2) * 1536);
        float4 w3 = *(const float4*)(wp + (size_t)(r0 + b * 4 + 3) * 1536);
        float x0 = g_mid[r0 + b * 4], x1 = g_mid[r0 + b * 4 + 1];
        float x2 = g_mid[r0 + b * 4 + 2], x3 = g_mid[r0 + b * 4 + 3];
        f4fma(acc, x0, w0); f4fma(acc, x1, w1); f4fma(acc, x2, w2); f4fma(acc, x3, w3);
    }
    acc = wred<2>(acc);
    if (lane < 2) part[wid * 2 + lane] = acc;
    __syncthreads();
    if (t < 2) {
        float4 s = part[t];
#pragma unroll
        for (int wi = 1; wi < 16; wi++) s = f4add(s, part[wi * 2 + t]);
        atomicAdd(&((float4*)out)[colTile * 2 + t], s);
    }
}

extern "C" void kernel_launch(void* const* d_in, const int* in_sizes, int n_in,
                              void* d_out, int out_size) {
    const float* x  = (const float*)d_in[0];
    const float* kp = (const float*)d_in[1];
    const float* vp = (const float*)d_in[2];
    const float* Wq = (const float*)d_in[3];
    const float* bq = (const float*)d_in[4];
    const float* Wk = (const float*)d_in[5];
    const float* bk = (const float*)d_in[6];
    const float* Wv = (const float*)d_in[7];
    const float* bv = (const float*)d_in[8];
    const float* Wo = (const float*)d_in[9];
    const float* bo = (const float*)d_in[10];
    const float* Wg = (const float*)d_in[11];
    const float* bg = (const float*)d_in[12];
    const float* Wu = (const float*)d_in[13];
    const float* bu = (const float*)d_in[14];
    const float* Wd = (const float*)d_in[15];
    const float* bd = (const float*)d_in[16];

    k_qkv   <<<640, 512>>>(x, Wq, Wk, Wv);
    k_attn  <<<512, 256>>>(kp, vp, bq, bk, bv);
    k_comb  <<<32,  256>>>(x, bo);
    k_wo    <<<384, 512>>>(Wo);
    k_gateup<<<768, 512>>>(Wg, bg, Wu, bu, bd, (float*)d_out);
    k_down  <<<384, 512>>>(Wd, (float*)d_out);
}

// round 9
// speedup vs baseline: 1.1014x; 1.1014x over previous
#include <cuda_runtime.h>

#define NQ 8
#define HD 256
#define S_TOT 8192
#define PAST 8191
#define HID 1536
#define INTER 6144
#define QDIM 2048
#define SCALE 0.0625f
#define NCHUNK 256          // 8192 / 32
#define CHUNK 32

// -------- scratch (device globals) --------
__device__ float g_qkv[2560];              // q[0:2048] (pre-scaled), k_new[2048:2304], v_new[2304:2560]
__device__ float g_avpart[NCHUNK * 2048];  // per-chunk partial AV: [c][h*256+d]
__device__ float g_stm[NCHUNK * 8];        // per-(chunk,head) local max
__device__ float g_stl[NCHUNK * 8];        // per-(chunk,head) local sum
__device__ float g_attn[QDIM];             // final attention output
__device__ float g_h1[HID];                // preset x+bo by k_comb; k_wo atomics add Wo part
__device__ float g_gup[16 * 2 * INTER];    // gate/up partials: [stripe][mat][6144]
__device__ float g_mid[INTER];             // gelu(gate)*up

static __device__ __forceinline__ float4 f4add(float4 a, float4 b) {
    a.x += b.x; a.y += b.y; a.z += b.z; a.w += b.w; return a;
}
static __device__ __forceinline__ void f4fma(float4& a, float s, float4 w) {
    a.x += s * w.x; a.y += s * w.y; a.z += s * w.z; a.w += s * w.w;
}
static __device__ __forceinline__ float gelu_exact(float v) {
    return 0.5f * v * (1.0f + erff(v * 0.70710678118654752f));
}
template<int PMIN>
static __device__ __forceinline__ float4 wred(float4 v) {
#pragma unroll
    for (int off = 16; off >= PMIN; off >>= 1) {
        v.x += __shfl_xor_sync(0xffffffffu, v.x, off);
        v.y += __shfl_xor_sync(0xffffffffu, v.y, off);
        v.z += __shfl_xor_sync(0xffffffffu, v.z, off);
        v.w += __shfl_xor_sync(0xffffffffu, v.w, off);
    }
    return v;
}

// ============ K1: QKV projection (+bias, q pre-scaled by SCALE) ============ (R6 verbatim)
__global__ __launch_bounds__(512) void k_qkv(
        const float* __restrict__ x,
        const float* __restrict__ Wq, const float* __restrict__ bq,
        const float* __restrict__ Wk, const float* __restrict__ bk,
        const float* __restrict__ Wv, const float* __restrict__ bv) {
    __shared__ float4 part[16 * 2];
    int t = threadIdx.x, lane = t & 31, wid = t >> 5;
    int c4 = t & 1, rg = t >> 1;
    int colBase = blockIdx.x * 8;
    const float* W; const float* bias; int ld, wcol; float sc;
    if (blockIdx.x < 256)      { W = Wq; bias = bq; ld = 2048; wcol = colBase;        sc = SCALE; }
    else if (blockIdx.x < 288) { W = Wk; bias = bk; ld = 256;  wcol = colBase - 2048; sc = 1.0f; }
    else                       { W = Wv; bias = bv; ld = 256;  wcol = colBase - 2304; sc = 1.0f; }
    const float* wp = W + wcol + c4 * 4;
    float4 acc = make_float4(0.f, 0.f, 0.f, 0.f);
    int r0 = rg * 6;
#pragma unroll
    for (int i = 0; i < 6; i++) {
        int r = r0 + i;
        float xv = __ldg(x + r);
        float4 w = *(const float4*)(wp + (size_t)r * ld);
        f4fma(acc, xv, w);
    }
    acc = wred<2>(acc);
    if (lane < 2) part[wid * 2 + lane] = acc;
    __syncthreads();
    if (t < 2) {
        float4 s = part[t];
#pragma unroll
        for (int w = 1; w < 16; w++) s = f4add(s, part[w * 2 + t]);
        int col = wcol + t * 4;
        float4 b = *(const float4*)(bias + col);
        s = f4add(s, b);
        s.x *= sc; s.y *= sc; s.z *= sc; s.w *= sc;
        *(float4*)&g_qkv[colBase + t * 4] = s;
    }
}

// ============ K2: fused flash-decode partial ============ (R6 verbatim)
__global__ __launch_bounds__(256, 2) void k_attn(
        const float* __restrict__ kp, const float* __restrict__ vp) {
    __shared__ float s_sm[8][CHUNK];
    __shared__ float4 red[4 * 8 * 64];
    int t = threadIdx.x, lane = t & 31, wid = t >> 5;
    int c = blockIdx.x;
    int sBase = c * CHUNK;
    float4 qa[8], qb[8];
#pragma unroll
    for (int h = 0; h < 8; h++) {
        qa[h] = *(const float4*)(g_qkv + h * 256 + lane * 8);
        qb[h] = *(const float4*)(g_qkv + h * 256 + lane * 8 + 4);
    }
#pragma unroll
    for (int it = 0; it < 2; it++) {
        int r0 = sBase + wid * 4 + it * 2;
        int r1 = r0 + 1;
        const float* kr0 = (r0 < PAST) ? (kp + (size_t)r0 * 256) : (g_qkv + 2048);
        const float* kr1 = (r1 < PAST) ? (kp + (size_t)r1 * 256) : (g_qkv + 2048);
        float4 ka0 = *(const float4*)(kr0 + lane * 8);
        float4 kb0 = *(const float4*)(kr0 + lane * 8 + 4);
        float4 ka1 = *(const float4*)(kr1 + lane * 8);
        float4 kb1 = *(const float4*)(kr1 + lane * 8 + 4);
        float a0[8], a1[8];
#pragma unroll
        for (int h = 0; h < 8; h++) {
            a0[h] = qa[h].x * ka0.x + qa[h].y * ka0.y + qa[h].z * ka0.z + qa[h].w * ka0.w
                  + qb[h].x * kb0.x + qb[h].y * kb0.y + qb[h].z * kb0.z + qb[h].w * kb0.w;
            a1[h] = qa[h].x * ka1.x + qa[h].y * ka1.y + qa[h].z * ka1.z + qa[h].w * ka1.w
                  + qb[h].x * kb1.x + qb[h].y * kb1.y + qb[h].z * kb1.z + qb[h].w * kb1.w;
        }
#pragma unroll
        for (int h = 0; h < 8; h++) {
#pragma unroll
            for (int off = 16; off; off >>= 1) {
                a0[h] += __shfl_xor_sync(0xffffffffu, a0[h], off);
                a1[h] += __shfl_xor_sync(0xffffffffu, a1[h], off);
            }
        }
        if (lane < 8) {
            s_sm[lane][wid * 4 + it * 2]     = a0[lane];
            s_sm[lane][wid * 4 + it * 2 + 1] = a1[lane];
        }
    }
    __syncthreads();
    {
        float s = s_sm[wid][lane];
        float m = s;
#pragma unroll
        for (int off = 16; off; off >>= 1) m = fmaxf(m, __shfl_xor_sync(0xffffffffu, m, off));
        float p = __expf(s - m);
        float l = p;
#pragma unroll
        for (int off = 16; off; off >>= 1) l += __shfl_xor_sync(0xffffffffu, l, off);
        s_sm[wid][lane] = p;
        if (lane == 0) { g_stm[c * 8 + wid] = m; g_stl[c * 8 + wid] = l; }
    }
    __syncthreads();
    int d4 = t & 63, g = t >> 6;
    float4 acc[8];
#pragma unroll
    for (int h = 0; h < 8; h++) acc[h] = make_float4(0.f, 0.f, 0.f, 0.f);
    float4 v[8];
#pragma unroll
    for (int j = 0; j < 8; j++) {
        int s = sBase + g * 8 + j;
        const float* vrow = (s < PAST) ? (vp + (size_t)s * 256) : (g_qkv + 2304);
        v[j] = *(const float4*)(vrow + d4 * 4);
    }
#pragma unroll
    for (int j = 0; j < 8; j++) {
        int pos = g * 8 + j;
#pragma unroll
        for (int h = 0; h < 8; h++) f4fma(acc[h], s_sm[h][pos], v[j]);
    }
#pragma unroll
    for (int h = 0; h < 8; h++) red[g * 512 + h * 64 + d4] = acc[h];
    __syncthreads();
    float4* outp = (float4*)(g_avpart + (size_t)c * 2048);
#pragma unroll
    for (int k = 0; k < 2; k++) {
        int o = t + k * 256;
        float4 s = f4add(f4add(red[o], red[512 + o]), f4add(red[1024 + o], red[1536 + o]));
        outp[o] = s;
    }
}

// ============ K3: combine partials -> g_attn; preset g_h1 = x + bo ============
__global__ __launch_bounds__(256) void k_comb(
        const float* __restrict__ x, const float* __restrict__ bo) {
    __shared__ float w_sm[NCHUNK * 8];
    __shared__ float4 red2[256];
    int t = threadIdx.x, lane = t & 31, wid = t >> 5;
    float mv[8], lv[8];
#pragma unroll
    for (int i = 0; i < 8; i++) {
        int c = lane * 8 + i;
        mv[i] = g_stm[c * 8 + wid];
        lv[i] = g_stl[c * 8 + wid];
    }
    float M = mv[0];
#pragma unroll
    for (int i = 1; i < 8; i++) M = fmaxf(M, mv[i]);
#pragma unroll
    for (int off = 16; off; off >>= 1) M = fmaxf(M, __shfl_xor_sync(0xffffffffu, M, off));
    float L = 0.f;
#pragma unroll
    for (int i = 0; i < 8; i++) L += __expf(mv[i] - M) * lv[i];
#pragma unroll
    for (int off = 16; off; off >>= 1) L += __shfl_xor_sync(0xffffffffu, L, off);
    float invL = 1.0f / L;
#pragma unroll
    for (int i = 0; i < 8; i++) {
        int c = lane * 8 + i;
        w_sm[c * 8 + wid] = __expf(mv[i] - M) * invL;
    }
    // preset g_h1 = x + bo (blocks 0..5 cover 1536 floats)
    if (blockIdx.x < 6) {
        int idx = blockIdx.x * 256 + t;
        g_h1[idx] = x[idx] + bo[idx];
    }
    __syncthreads();
    int oLoc = t >> 3, sl = t & 7;
    int o = blockIdx.x * 32 + oLoc;
    int h = o >> 6;
    float4 acc = make_float4(0.f, 0.f, 0.f, 0.f);
#pragma unroll
    for (int b = 0; b < 4; b++) {
        float4 vv[8];
#pragma unroll
        for (int i = 0; i < 8; i++) {
            int c = sl * 32 + b * 8 + i;
            vv[i] = *(const float4*)(g_avpart + (size_t)c * 2048 + o * 4);
        }
#pragma unroll
        for (int i = 0; i < 8; i++) {
            int c = sl * 32 + b * 8 + i;
            f4fma(acc, w_sm[c * 8 + h], vv[i]);
        }
    }
    red2[t] = acc;
    __syncthreads();
    if (t < 32) {
        float4 s = red2[t * 8];
#pragma unroll
        for (int i = 1; i < 8; i++) s = f4add(s, red2[t * 8 + i]);
        ((float4*)g_attn)[blockIdx.x * 32 + t] = s;
    }
}

// ============ K4: g_h1 += attn @ Wo  (DENSE: warp owns 64 contiguous cols) ============
// 96 blocks x 256 thr (8 warps). stripe = b/3 (64 rows), warp's colgroup = (b%3)*8+w.
__global__ __launch_bounds__(256) void k_wo(const float* __restrict__ Wo) {
    __shared__ float att_s[64];
    int t = threadIdx.x, lane = t & 31, wid = t >> 5;
    int stripe = blockIdx.x / 3;            // 0..31
    int cg = (blockIdx.x % 3) * 8 + wid;    // 0..23
    int col = cg * 64 + lane * 2;
    int r0 = stripe * 64;
    if (t < 64) att_s[t] = g_attn[r0 + t];
    __syncthreads();
    const float* wp = Wo + (size_t)r0 * 1536 + col;
    float ax = 0.f, ay = 0.f;
#pragma unroll
    for (int b = 0; b < 8; b++) {
        float2 w[8]; float xs[8];
#pragma unroll
        for (int i = 0; i < 8; i++)
            w[i] = *(const float2*)(wp + (size_t)(b * 8 + i) * 1536);
#pragma unroll
        for (int i = 0; i < 8; i++) xs[i] = att_s[b * 8 + i];
#pragma unroll
        for (int i = 0; i < 8; i++) { ax += xs[i] * w[i].x; ay += xs[i] * w[i].y; }
    }
    atomicAdd(&g_h1[col], ax);
    atomicAdd(&g_h1[col + 1], ay);
}

// ============ K5: gate/up partials (DENSE: warp owns 128 contiguous cols) ============
// 192 blocks x 256 thr. stripe = b/12 (96 rows); warp's g = (b%12)*8+w (0..95);
// mat = g/48 (0=Wg, 1=Wu); colgroup = g%48.
__global__ __launch_bounds__(256) void k_gu(
        const float* __restrict__ Wg, const float* __restrict__ Wu) {
    __shared__ float h1s[96];
    int t = threadIdx.x, lane = t & 31, wid = t >> 5;
    int stripe = blockIdx.x / 12;           // 0..15
    int g = (blockIdx.x % 12) * 8 + wid;    // 0..95
    int mat = g / 48;
    int cg = g % 48;
    int col = cg * 128 + lane * 4;
    int r0 = stripe * 96;
    if (t < 96) h1s[t] = g_h1[r0 + t];
    __syncthreads();
    const float* W = mat ? Wu : Wg;
    const float* wp = W + (size_t)r0 * 6144 + col;
    float4 acc = make_float4(0.f, 0.f, 0.f, 0.f);
#pragma unroll
    for (int b = 0; b < 12; b++) {
        float4 w[8]; float xs[8];
#pragma unroll
        for (int i = 0; i < 8; i++)
            w[i] = *(const float4*)(wp + (size_t)(b * 8 + i) * 6144);
#pragma unroll
        for (int i = 0; i < 8; i++) xs[i] = h1s[b * 8 + i];
#pragma unroll
        for (int i = 0; i < 8; i++) f4fma(acc, xs[i], w[i]);
    }
    *(float4*)&g_gup[((size_t)(stripe * 2 + mat)) * INTER + col] = acc;
}

// ============ K6: mid = gelu(sum gate + bg) * (sum up + bu); preset out = h1 + bd ====
// 15 blocks x 512 thr. Blocks 0-11: one col each of 6144. Blocks 12-14: preset out.
__global__ __launch_bounds__(512) void k_mid(
        const float* __restrict__ bg, const float* __restrict__ bu,
        const float* __restrict__ bd, float* __restrict__ out) {
    int t = threadIdx.x;
    if (blockIdx.x < 12) {
        int col = blockIdx.x * 512 + t;
        float ga[16], ua[16];
#pragma unroll
        for (int s = 0; s < 16; s++) ga[s] = g_gup[(size_t)(s * 2) * INTER + col];
#pragma unroll
        for (int s = 0; s < 16; s++) ua[s] = g_gup[(size_t)(s * 2 + 1) * INTER + col];
        float gacc = bg[col], uacc = bu[col];
#pragma unroll
        for (int s = 0; s < 16; s++) { gacc += ga[s]; uacc += ua[s]; }
        g_mid[col] = gelu_exact(gacc) * uacc;
    } else {
        int idx = (blockIdx.x - 12) * 512 + t;
        out[idx] = g_h1[idx] + bd[idx];
    }
}

// ============ K7: out += mid @ Wd  (DENSE: warp owns 64 contiguous cols) ============
// 144 blocks x 256 thr. stripe = b/3 (128 rows); colgroup = (b%3)*8+w.
__global__ __launch_bounds__(256) void k_down(
        const float* __restrict__ Wd, float* __restrict__ out) {
    __shared__ float mids[128];
    int t = threadIdx.x, lane = t & 31, wid = t >> 5;
    int stripe = blockIdx.x / 3;            // 0..47
    int cg = (blockIdx.x % 3) * 8 + wid;    // 0..23
    int col = cg * 64 + lane * 2;
    int r0 = stripe * 128;
    if (t < 128) mids[t] = g_mid[r0 + t];
    __syncthreads();
    const float* wp = Wd + (size_t)r0 * 1536 + col;
    float ax = 0.f, ay = 0.f;
#pragma unroll
    for (int b = 0; b < 16; b++) {
        float2 w[8]; float xs[8];
#pragma unroll
        for (int i = 0; i < 8; i++)
            w[i] = *(const float2*)(wp + (size_t)(b * 8 + i) * 1536);
#pragma unroll
        for (int i = 0; i < 8; i++) xs[i] = mids[b * 8 + i];
#pragma unroll
        for (int i = 0; i < 8; i++) { ax += xs[i] * w[i].x; ay += xs[i] * w[i].y; }
    }
    atomicAdd(&out[col], ax);
    atomicAdd(&out[col + 1], ay);
}

extern "C" void kernel_launch(void* const* d_in, const int* in_sizes, int n_in,
                              void* d_out, int out_size) {
    const float* x  = (const float*)d_in[0];
    const float* kp = (const float*)d_in[1];
    const float* vp = (const float*)d_in[2];
    const float* Wq = (const float*)d_in[3];
    const float* bq = (const float*)d_in[4];
    const float* Wk = (const float*)d_in[5];
    const float* bk = (const float*)d_in[6];
    const float* Wv = (const float*)d_in[7];
    const float* bv = (const float*)d_in[8];
    const float* Wo = (const float*)d_in[9];
    const float* bo = (const float*)d_in[10];
    const float* Wg = (const float*)d_in[11];
    const float* bg = (const float*)d_in[12];
    const float* Wu = (const float*)d_in[13];
    const float* bu = (const float*)d_in[14];
    const float* Wd = (const float*)d_in[15];
    const float* bd = (const float*)d_in[16];

    k_qkv <<<320, 512>>>(x, Wq, bq, Wk, bk, Wv, bv);
    k_attn<<<256, 256>>>(kp, vp);
    k_comb<<<16,  256>>>(x, bo);
    k_wo  <<<96,  256>>>(Wo);
    k_gu  <<<192, 256>>>(Wg, Wu);
    k_mid <<<15,  512>>>(bg, bu, bd, (float*)d_out);
    k_down<<<144, 256>>>(Wd, (float*)d_out);
}